// round 15
// baseline (speedup 1.0000x reference)
#include <cuda_runtime.h>
#include <cuda_fp16.h>
#include <math.h>
#include <stdint.h>

#define NN   50000
#define FDIM 128
#define CDIM 40
#define NE   600000
#define NET  (NE + NN)
#define NSCB 49               // ceil(NN/1024) scan blocks

// bit-casts (no standard intrinsics exist for half2<->uint)
static __device__ __forceinline__ unsigned int h2_as_u32(__half2 h) {
    return *reinterpret_cast<unsigned int*>(&h);
}
static __device__ __forceinline__ __half2 u32_as_h2(unsigned int u) {
    return *reinterpret_cast<__half2*>(&u);
}

// ---------------- device scratch (no allocations allowed) ----------------
__device__ int     g_deg[NN];            // zero at load (BSS); re-zeroed by k_scan3 each call
__device__ float   g_dinv[NN];
__device__ int     g_rowptr[NN + 1];
__device__ int     g_fill[NN];
__device__ int     g_bsum[64];
__device__ int2    g_edge[NET];          // (src, norm-bits) packed
__device__ __half2 g_hh [NN * (FDIM/2)]; // layer-1 GEMM output (fp16)
__device__ __half2 g_hh2[NN * (FDIM/2)]; // layer-2 GEMM output (fp16)

// ---------------- graph preprocessing ----------------
__global__ void k_hist(const int* __restrict__ ei) {
    int e = blockIdx.x * blockDim.x + threadIdx.x;
    if (e < NE) atomicAdd(&g_deg[ei[NE + e]], 1);
}

// phase 1: per-block (1024-wide) exclusive scan of (deg+1); also dinv
__global__ __launch_bounds__(1024) void k_scan1() {
    __shared__ int warp_sums[32];
    int tid  = threadIdx.x;
    int lane = tid & 31;
    int wid  = tid >> 5;
    int i = blockIdx.x * 1024 + tid;
    int v = 0;
    if (i < NN) {
        v = g_deg[i] + 1;                       // +1 self loop
        g_dinv[i] = rsqrtf((float)v);
    }
    int x = v;
    #pragma unroll
    for (int o = 1; o < 32; o <<= 1) {
        int y = __shfl_up_sync(0xffffffffu, x, o);
        if (lane >= o) x += y;
    }
    if (lane == 31) warp_sums[wid] = x;
    __syncthreads();
    if (wid == 0) {
        int ws = warp_sums[lane];
        #pragma unroll
        for (int o = 1; o < 32; o <<= 1) {
            int y = __shfl_up_sync(0xffffffffu, ws, o);
            if (lane >= o) ws += y;
        }
        warp_sums[lane] = ws;
    }
    __syncthreads();
    int excl = (wid ? warp_sums[wid - 1] : 0) + x - v;
    if (i < NN) g_rowptr[i] = excl;
    if (tid == 1023) g_bsum[blockIdx.x] = excl + v;
}

// phase 2+3 fused: block-offset add, zero fill counters, re-zero g_deg for next call
__global__ __launch_bounds__(1024) void k_scan3() {
    __shared__ int s_off;
    int b = blockIdx.x;
    if (threadIdx.x < 32) {
        int lane = threadIdx.x;
        int acc = 0;
        for (int idx = lane; idx < b; idx += 32) acc += g_bsum[idx];   // <=2 iters
        #pragma unroll
        for (int o = 16; o; o >>= 1) acc += __shfl_xor_sync(0xffffffffu, acc, o);
        if (lane == 0) s_off = acc;
    }
    __syncthreads();
    int i = b * 1024 + threadIdx.x;
    if (i < NN) {
        g_rowptr[i] += s_off;
        g_fill[i] = 0;
        g_deg[i]  = 0;
    }
    if (b == 0 && threadIdx.x == 0) g_rowptr[NN] = NET;
}

__global__ void k_fill(const int* __restrict__ ei) {
    int e = blockIdx.x * blockDim.x + threadIdx.x;
    if (e >= NET) return;
    int s, d;
    if (e < NE) { s = ei[e]; d = ei[NE + e]; }
    else        { s = d = e - NE; }                    // self loop
    int p = g_rowptr[d] + atomicAdd(&g_fill[d], 1);
    g_edge[p] = make_int2(s, __float_as_int(g_dinv[s] * g_dinv[d]));
}

// ================= shared HMMA plumbing (sm_80+ PTX; valid on compute_103) =================
#define LDH 136                        // row stride in halves (16B-aligned, conflict-free)
#define GT_BLOCKS ((NN + 127) / 128)

__device__ __forceinline__ uint32_t smem_u32(const void* p) {
    uint32_t a;
    asm("{ .reg .u64 t; cvta.to.shared.u64 t, %1; cvt.u32.u64 %0, t; }" : "=r"(a) : "l"(p));
    return a;
}
__device__ __forceinline__ void ldmx4(uint32_t& r0, uint32_t& r1, uint32_t& r2, uint32_t& r3,
                                      uint32_t addr) {
    asm volatile("ldmatrix.sync.aligned.m8n8.x4.shared.b16 {%0,%1,%2,%3}, [%4];"
                 : "=r"(r0), "=r"(r1), "=r"(r2), "=r"(r3) : "r"(addr));
}
__device__ __forceinline__ void ldmx2(uint32_t& r0, uint32_t& r1, uint32_t addr) {
    asm volatile("ldmatrix.sync.aligned.m8n8.x2.shared.b16 {%0,%1}, [%2];"
                 : "=r"(r0), "=r"(r1) : "r"(addr));
}
__device__ __forceinline__ void mma16816(float* c, uint32_t a0, uint32_t a1, uint32_t a2,
                                         uint32_t a3, uint32_t b0, uint32_t b1) {
    asm volatile(
        "mma.sync.aligned.m16n8k16.row.col.f32.f16.f16.f32 "
        "{%0,%1,%2,%3}, {%4,%5,%6,%7}, {%8,%9}, {%0,%1,%2,%3};"
        : "+f"(c[0]), "+f"(c[1]), "+f"(c[2]), "+f"(c[3])
        : "r"(a0), "r"(a1), "r"(a2), "r"(a3), "r"(b0), "r"(b1));
}

// warp-level CSR aggregation of one node row from src buffer (fp16 rows, 32 uint2/row).
// returns fp32 accumulation for this lane's 4 columns.
__device__ __forceinline__ float4 agg_row(const uint2* __restrict__ hh, int node, int lane) {
    int p0 = g_rowptr[node], p1 = g_rowptr[node + 1];
    float4 acc = make_float4(0.f, 0.f, 0.f, 0.f);
    for (int p = p0; p < p1; p++) {
        int2  e = g_edge[p];
        float w = __int_as_float(e.y);
        uint2 v = hh[e.x * 32 + lane];
        float2 f0 = __half22float2(u32_as_h2(v.x));
        float2 f1 = __half22float2(u32_as_h2(v.y));
        acc.x += w * f0.x; acc.y += w * f0.y;
        acc.z += w * f1.x; acc.w += w * f1.y;
    }
    return acc;
}

// ================= HMMA GEMM (layer 1): g_hh = fp16(x @ W1) =================
#define SM_Ah 0
#define SM_Bh (128 * LDH)
#define SMEM_TC (2 * 128 * LDH * 2)    // 69,632 B

__global__ __launch_bounds__(256) void k_gemm_tc(const float* __restrict__ A,
                                                 const float* __restrict__ W) {
    extern __shared__ __half smem[];
    int tid  = threadIdx.x;
    int wid  = tid >> 5;
    int lane = tid & 31;
    int row0 = blockIdx.x * 128;

    // A tile fp32 -> fp16
    #pragma unroll
    for (int it = 0; it < 8; it++) {
        int i   = tid + it * 256;
        int row = i >> 4;
        int cc  = (i & 15) * 8;
        float4 v0 = make_float4(0.f, 0.f, 0.f, 0.f), v1 = v0;
        int r = row0 + row;
        if (r < NN) {
            v0 = *(const float4*)&A[r * FDIM + cc];
            v1 = *(const float4*)&A[r * FDIM + cc + 4];
        }
        uint4 pk;
        pk.x = h2_as_u32(__floats2half2_rn(v0.x, v0.y));
        pk.y = h2_as_u32(__floats2half2_rn(v0.z, v0.w));
        pk.z = h2_as_u32(__floats2half2_rn(v1.x, v1.y));
        pk.w = h2_as_u32(__floats2half2_rn(v1.z, v1.w));
        *(uint4*)&smem[SM_Ah + row * LDH + cc] = pk;
    }
    // BT[n][k] = W[k][n]
    {
        int n  = tid & 127;
        int k0 = (tid >> 7) * 64;
        #pragma unroll 8
        for (int kk = 0; kk < 64; kk++) {
            int k = k0 + kk;
            smem[SM_Bh + n * LDH + k] = __float2half_rn(W[k * FDIM + n]);
        }
    }
    __syncthreads();

    uint32_t sbA = smem_u32(&smem[SM_Ah]);
    uint32_t sbB = smem_u32(&smem[SM_Bh]);
    int m0 = (wid >> 1) * 32;
    int n0 = (wid & 1) * 64;

    float c[2][8][4];
    #pragma unroll
    for (int mi = 0; mi < 2; mi++)
        #pragma unroll
        for (int nj = 0; nj < 8; nj++)
            #pragma unroll
            for (int q = 0; q < 4; q++) c[mi][nj][q] = 0.f;

    int a_row = lane & 15;
    int a_kof = (lane >> 4) * 8;
    int b_row = lane & 7;
    int b_kof = ((lane >> 3) & 1) * 8;

    #pragma unroll
    for (int ks = 0; ks < 8; ks++) {
        int k0 = ks * 16;
        uint32_t a[2][4];
        #pragma unroll
        for (int mi = 0; mi < 2; mi++) {
            uint32_t addr = sbA + (uint32_t)((m0 + mi * 16 + a_row) * LDH + k0 + a_kof) * 2;
            ldmx4(a[mi][0], a[mi][1], a[mi][2], a[mi][3], addr);
        }
        uint32_t b[8][2];
        #pragma unroll
        for (int nj = 0; nj < 8; nj++) {
            uint32_t addr = sbB + (uint32_t)((n0 + nj * 8 + b_row) * LDH + k0 + b_kof) * 2;
            ldmx2(b[nj][0], b[nj][1], addr);
        }
        #pragma unroll
        for (int mi = 0; mi < 2; mi++)
            #pragma unroll
            for (int nj = 0; nj < 8; nj++)
                mma16816(c[mi][nj], a[mi][0], a[mi][1], a[mi][2], a[mi][3],
                         b[nj][0], b[nj][1]);
    }

    int tr = lane >> 2;
    int tc = (lane & 3) * 2;
    #pragma unroll
    for (int mi = 0; mi < 2; mi++) {
        #pragma unroll
        for (int nj = 0; nj < 8; nj++) {
            int col = n0 + nj * 8 + tc;
            int r0g = row0 + m0 + mi * 16 + tr;
            int r1g = r0g + 8;
            if (r0g < NN)
                g_hh[r0g * (FDIM/2) + (col >> 1)] = __floats2half2_rn(c[mi][nj][0], c[mi][nj][1]);
            if (r1g < NN)
                g_hh[r1g * (FDIM/2) + (col >> 1)] = __floats2half2_rn(c[mi][nj][2], c[mi][nj][3]);
        }
    }
}

// ===== FUSED: agg1(relu,+b1) from g_hh -> SMEM A -> HMMA with W2 -> g_hh2 =====
__global__ __launch_bounds__(256) void k_agg_gemm(const float* __restrict__ b1,
                                                  const float* __restrict__ W) {
    extern __shared__ __half smem[];
    int tid  = threadIdx.x;
    int wid  = tid >> 5;
    int lane = tid & 31;
    int row0 = blockIdx.x * 128;

    // stage B = W2^T
    {
        int n  = tid & 127;
        int k0 = (tid >> 7) * 64;
        #pragma unroll 8
        for (int kk = 0; kk < 64; kk++) {
            int k = k0 + kk;
            smem[SM_Bh + n * LDH + k] = __float2half_rn(W[k * FDIM + n]);
        }
    }
    // stage A via CSR aggregation from g_hh (fp32 acc, +bias, relu, fp16 convert)
    {
        const uint2* hh = (const uint2*)g_hh;
        float4 bv = *(const float4*)&b1[lane * 4];
        for (int j = wid; j < 128; j += 8) {
            int node = row0 + j;
            uint2 st = make_uint2(0u, 0u);
            if (node < NN) {
                float4 acc = agg_row(hh, node, lane);
                acc.x = fmaxf(acc.x + bv.x, 0.f);
                acc.y = fmaxf(acc.y + bv.y, 0.f);
                acc.z = fmaxf(acc.z + bv.z, 0.f);
                acc.w = fmaxf(acc.w + bv.w, 0.f);
                st.x = h2_as_u32(__floats2half2_rn(acc.x, acc.y));
                st.y = h2_as_u32(__floats2half2_rn(acc.z, acc.w));
            }
            *(uint2*)&smem[SM_Ah + j * LDH + lane * 4] = st;
        }
    }
    __syncthreads();

    uint32_t sbA = smem_u32(&smem[SM_Ah]);
    uint32_t sbB = smem_u32(&smem[SM_Bh]);
    int m0 = (wid >> 1) * 32;
    int n0 = (wid & 1) * 64;

    float c[2][8][4];
    #pragma unroll
    for (int mi = 0; mi < 2; mi++)
        #pragma unroll
        for (int nj = 0; nj < 8; nj++)
            #pragma unroll
            for (int q = 0; q < 4; q++) c[mi][nj][q] = 0.f;

    int a_row = lane & 15;
    int a_kof = (lane >> 4) * 8;
    int b_row = lane & 7;
    int b_kof = ((lane >> 3) & 1) * 8;

    #pragma unroll
    for (int ks = 0; ks < 8; ks++) {
        int k0 = ks * 16;
        uint32_t a[2][4];
        #pragma unroll
        for (int mi = 0; mi < 2; mi++) {
            uint32_t addr = sbA + (uint32_t)((m0 + mi * 16 + a_row) * LDH + k0 + a_kof) * 2;
            ldmx4(a[mi][0], a[mi][1], a[mi][2], a[mi][3], addr);
        }
        uint32_t b[8][2];
        #pragma unroll
        for (int nj = 0; nj < 8; nj++) {
            uint32_t addr = sbB + (uint32_t)((n0 + nj * 8 + b_row) * LDH + k0 + b_kof) * 2;
            ldmx2(b[nj][0], b[nj][1], addr);
        }
        #pragma unroll
        for (int mi = 0; mi < 2; mi++)
            #pragma unroll
            for (int nj = 0; nj < 8; nj++)
                mma16816(c[mi][nj], a[mi][0], a[mi][1], a[mi][2], a[mi][3],
                         b[nj][0], b[nj][1]);
    }

    int tr = lane >> 2;
    int tc = (lane & 3) * 2;
    #pragma unroll
    for (int mi = 0; mi < 2; mi++) {
        #pragma unroll
        for (int nj = 0; nj < 8; nj++) {
            int col = n0 + nj * 8 + tc;
            int r0g = row0 + m0 + mi * 16 + tr;
            int r1g = r0g + 8;
            if (r0g < NN)
                g_hh2[r0g * (FDIM/2) + (col >> 1)] = __floats2half2_rn(c[mi][nj][0], c[mi][nj][1]);
            if (r1g < NN)
                g_hh2[r1g * (FDIM/2) + (col >> 1)] = __floats2half2_rn(c[mi][nj][2], c[mi][nj][3]);
        }
    }
}

// ===== FUSED: agg2(+b2) from g_hh2 -> xemb (output) + split-fp16 head -> log_softmax =====
#define LG_XhO 0
#define LG_XlO (128 * LDH)
#define LG_WhO (2 * 128 * LDH)
#define LG_WlO (2 * 128 * LDH + CDIM * LDH)
#define LG_BLO (2 * 128 * LDH + 2 * CDIM * LDH)      // half-index where bias floats start
#define SMEM_LG (LG_BLO * 2 + CDIM * 4)

__global__ __launch_bounds__(256) void k_agg_head(const float* __restrict__ b2,
                                                  const float* __restrict__ Wl,
                                                  const float* __restrict__ bl,
                                                  float* __restrict__ xemb,
                                                  float* __restrict__ out) {
    extern __shared__ __half smem[];
    float* sbl = (float*)&smem[LG_BLO];
    int tid  = threadIdx.x;
    int wid  = tid >> 5;
    int lane = tid & 31;
    int row0 = blockIdx.x * 128;

    // stage WlT hi/lo + bl
    for (int idx = tid; idx < CDIM * FDIM; idx += 256) {
        int n = idx >> 7;
        int k = idx & 127;
        float f = Wl[k * CDIM + n];
        __half h = __float2half_rn(f);
        smem[LG_WhO + n * LDH + k] = h;
        smem[LG_WlO + n * LDH + k] = __float2half_rn(f - __half2float(h));
    }
    if (tid < CDIM) sbl[tid] = bl[tid];

    // stage X via CSR aggregation from g_hh2; also write xemb output
    {
        const uint2* hh = (const uint2*)g_hh2;
        float4 bv = *(const float4*)&b2[lane * 4];
        for (int j = wid; j < 128; j += 8) {
            int node = row0 + j;
            uint2 sh = make_uint2(0u, 0u), sl = make_uint2(0u, 0u);
            if (node < NN) {
                float4 acc = agg_row(hh, node, lane);
                acc.x += bv.x; acc.y += bv.y; acc.z += bv.z; acc.w += bv.w;
                *(float4*)&xemb[node * FDIM + lane * 4] = acc;
                float v[4] = {acc.x, acc.y, acc.z, acc.w};
                __half hi[4], lo[4];
                #pragma unroll
                for (int q = 0; q < 4; q++) {
                    hi[q] = __float2half_rn(v[q]);
                    lo[q] = __float2half_rn(v[q] - __half2float(hi[q]));
                }
                sh = *(uint2*)hi;
                sl = *(uint2*)lo;
            }
            *(uint2*)&smem[LG_XhO + j * LDH + lane * 4] = sh;
            *(uint2*)&smem[LG_XlO + j * LDH + lane * 4] = sl;
        }
    }
    __syncthreads();

    uint32_t sbXh = smem_u32(&smem[LG_XhO]);
    uint32_t sbXl = smem_u32(&smem[LG_XlO]);
    uint32_t sbWh = smem_u32(&smem[LG_WhO]);
    uint32_t sbWl = smem_u32(&smem[LG_WlO]);

    int m0 = wid * 16;
    float c[5][4];
    #pragma unroll
    for (int nj = 0; nj < 5; nj++)
        #pragma unroll
        for (int q = 0; q < 4; q++) c[nj][q] = 0.f;

    int a_row = lane & 15;
    int a_kof = (lane >> 4) * 8;
    int b_row = lane & 7;
    int b_kof = ((lane >> 3) & 1) * 8;

    #pragma unroll
    for (int ks = 0; ks < 8; ks++) {
        int k0 = ks * 16;
        uint32_t ah[4], al[4];
        uint32_t aaddr = (uint32_t)((m0 + a_row) * LDH + k0 + a_kof) * 2;
        ldmx4(ah[0], ah[1], ah[2], ah[3], sbXh + aaddr);
        ldmx4(al[0], al[1], al[2], al[3], sbXl + aaddr);
        #pragma unroll
        for (int nj = 0; nj < 5; nj++) {
            uint32_t baddr = (uint32_t)((nj * 8 + b_row) * LDH + k0 + b_kof) * 2;
            uint32_t bh0, bh1, bl0, bl1;
            ldmx2(bh0, bh1, sbWh + baddr);
            ldmx2(bl0, bl1, sbWl + baddr);
            mma16816(c[nj], ah[0], ah[1], ah[2], ah[3], bh0, bh1);   // xh*wh
            mma16816(c[nj], al[0], al[1], al[2], al[3], bh0, bh1);   // xl*wh
            mma16816(c[nj], ah[0], ah[1], ah[2], ah[3], bl0, bl1);   // xh*wl
        }
    }

    int tr  = lane >> 2;
    int tc2 = (lane & 3) * 2;
    #pragma unroll
    for (int nj = 0; nj < 5; nj++) {
        float b0 = sbl[nj * 8 + tc2], b1v = sbl[nj * 8 + tc2 + 1];
        c[nj][0] += b0; c[nj][1] += b1v;
        c[nj][2] += b0; c[nj][3] += b1v;
    }

    float mA = -INFINITY, mB = -INFINITY;
    #pragma unroll
    for (int nj = 0; nj < 5; nj++) {
        mA = fmaxf(mA, fmaxf(c[nj][0], c[nj][1]));
        mB = fmaxf(mB, fmaxf(c[nj][2], c[nj][3]));
    }
    mA = fmaxf(mA, __shfl_xor_sync(0xffffffffu, mA, 1));
    mA = fmaxf(mA, __shfl_xor_sync(0xffffffffu, mA, 2));
    mB = fmaxf(mB, __shfl_xor_sync(0xffffffffu, mB, 1));
    mB = fmaxf(mB, __shfl_xor_sync(0xffffffffu, mB, 2));
    float sA = 0.f, sB = 0.f;
    #pragma unroll
    for (int nj = 0; nj < 5; nj++) {
        sA += expf(c[nj][0] - mA) + expf(c[nj][1] - mA);
        sB += expf(c[nj][2] - mB) + expf(c[nj][3] - mB);
    }
    sA += __shfl_xor_sync(0xffffffffu, sA, 1);
    sA += __shfl_xor_sync(0xffffffffu, sA, 2);
    sB += __shfl_xor_sync(0xffffffffu, sB, 1);
    sB += __shfl_xor_sync(0xffffffffu, sB, 2);
    float dA = mA + logf(sA), dB = mB + logf(sB);

    int rA = row0 + m0 + tr;
    int rB = rA + 8;
    #pragma unroll
    for (int nj = 0; nj < 5; nj++) {
        int col = nj * 8 + tc2;
        if (rA < NN) {
            float2 o = make_float2(c[nj][0] - dA, c[nj][1] - dA);
            *(float2*)&out[rA * CDIM + col] = o;
        }
        if (rB < NN) {
            float2 o = make_float2(c[nj][2] - dB, c[nj][3] - dB);
            *(float2*)&out[rB * CDIM + col] = o;
        }
    }
}

// ---------------- launcher (graph-capture safe; fork gemm1 beside preproc) ----------------
extern "C" void kernel_launch(void* const* d_in, const int* in_sizes, int n_in,
                              void* d_out, int out_size) {
    const float* x  = (const float*)d_in[0];
    const int*   ei = (const int*)d_in[1];     // JAX int64 request silently yields int32
    const float* W1 = (const float*)d_in[2];
    const float* b1 = (const float*)d_in[3];
    const float* W2 = (const float*)d_in[4];
    const float* b2 = (const float*)d_in[5];
    const float* Wl = (const float*)d_in[6];
    const float* bl = (const float*)d_in[7];
    float* out  = (float*)d_out;
    float* xemb = out + (size_t)NN * CDIM;     // second output lives after logits

    cudaFuncSetAttribute(k_gemm_tc,  cudaFuncAttributeMaxDynamicSharedMemorySize, SMEM_TC);
    cudaFuncSetAttribute(k_agg_gemm, cudaFuncAttributeMaxDynamicSharedMemorySize, SMEM_TC);
    cudaFuncSetAttribute(k_agg_head, cudaFuncAttributeMaxDynamicSharedMemorySize, SMEM_LG);

    // fork: gemm1 depends only on (x, W1) — run beside the preproc chain.
    cudaStream_t s2;
    cudaEvent_t  evFork, evJoin;
    cudaStreamCreateWithFlags(&s2, cudaStreamNonBlocking);
    cudaEventCreateWithFlags(&evFork, cudaEventDisableTiming);
    cudaEventCreateWithFlags(&evJoin, cudaEventDisableTiming);

    cudaEventRecord(evFork, 0);
    cudaStreamWaitEvent(s2, evFork, 0);
    k_gemm_tc<<<GT_BLOCKS, 256, SMEM_TC, s2>>>(x, W1);     // layer-1 GEMM on side branch
    cudaEventRecord(evJoin, s2);

    // preprocessing chain on the main (capture) stream
    k_hist <<<(NE + 255) / 256, 256>>>(ei);
    k_scan1<<<NSCB, 1024>>>();
    k_scan3<<<NSCB, 1024>>>();
    k_fill <<<(NET + 255) / 256, 256>>>(ei);

    cudaStreamWaitEvent(0, evJoin, 0);   // join: agg_gemm needs both CSR and g_hh

    // fused layer-1-agg + layer-2 GEMM:  g_hh2 = fp16( relu(agg(g_hh)+b1) @ W2 )
    k_agg_gemm<<<GT_BLOCKS, 256, SMEM_TC>>>(b1, W2);

    // fused layer-2-agg + head: xemb = agg(g_hh2)+b2 ; out = log_softmax(xemb @ Wl + bl)
    k_agg_head<<<GT_BLOCKS, 256, SMEM_LG>>>(b2, Wl, bl, xemb, out);
}

// round 16
// speedup vs baseline: 1.4530x; 1.4530x over previous
#include <cuda_runtime.h>
#include <cuda_fp16.h>
#include <math.h>
#include <stdint.h>

#define NN   50000
#define FDIM 128
#define CDIM 40
#define NE   600000
#define NET  (NE + NN)
#define NSCB 49               // ceil(NN/1024) scan blocks

// bit-casts (no standard intrinsics exist for half2<->uint)
static __device__ __forceinline__ unsigned int h2_as_u32(__half2 h) {
    return *reinterpret_cast<unsigned int*>(&h);
}
static __device__ __forceinline__ __half2 u32_as_h2(unsigned int u) {
    return *reinterpret_cast<__half2*>(&u);
}

// ---------------- device scratch (no allocations allowed) ----------------
__device__ int     g_deg[NN];            // zero at load (BSS); re-zeroed by k_scan3 each call
__device__ float   g_dinv[NN];
__device__ int     g_rowptr[NN + 1];
__device__ int     g_fill[NN];
__device__ int     g_bsum[64];
__device__ int2    g_edge[NET];          // (src, norm-bits) packed
__device__ __half2 g_hh[NN * (FDIM/2)];  // layer-1 GEMM output (fp16)
__device__ __half2 g_ah[NN * (FDIM/2)];  // layer-1 activations (fp16) = relu(agg(g_hh)+b1)

// ---------------- graph preprocessing ----------------
__global__ void k_hist(const int* __restrict__ ei) {
    int e = blockIdx.x * blockDim.x + threadIdx.x;
    if (e < NE) atomicAdd(&g_deg[ei[NE + e]], 1);
}

// phase 1: per-block (1024-wide) exclusive scan of (deg+1); also dinv
__global__ __launch_bounds__(1024) void k_scan1() {
    __shared__ int warp_sums[32];
    int tid  = threadIdx.x;
    int lane = tid & 31;
    int wid  = tid >> 5;
    int i = blockIdx.x * 1024 + tid;
    int v = 0;
    if (i < NN) {
        v = g_deg[i] + 1;                       // +1 self loop
        g_dinv[i] = rsqrtf((float)v);
    }
    int x = v;
    #pragma unroll
    for (int o = 1; o < 32; o <<= 1) {
        int y = __shfl_up_sync(0xffffffffu, x, o);
        if (lane >= o) x += y;
    }
    if (lane == 31) warp_sums[wid] = x;
    __syncthreads();
    if (wid == 0) {
        int ws = warp_sums[lane];
        #pragma unroll
        for (int o = 1; o < 32; o <<= 1) {
            int y = __shfl_up_sync(0xffffffffu, ws, o);
            if (lane >= o) ws += y;
        }
        warp_sums[lane] = ws;
    }
    __syncthreads();
    int excl = (wid ? warp_sums[wid - 1] : 0) + x - v;
    if (i < NN) g_rowptr[i] = excl;
    if (tid == 1023) g_bsum[blockIdx.x] = excl + v;
}

// phase 2+3 fused: block-offset add, zero fill counters, re-zero g_deg for next call
__global__ __launch_bounds__(1024) void k_scan3() {
    __shared__ int s_off;
    int b = blockIdx.x;
    if (threadIdx.x < 32) {
        int lane = threadIdx.x;
        int acc = 0;
        for (int idx = lane; idx < b; idx += 32) acc += g_bsum[idx];   // <=2 iters
        #pragma unroll
        for (int o = 16; o; o >>= 1) acc += __shfl_xor_sync(0xffffffffu, acc, o);
        if (lane == 0) s_off = acc;
    }
    __syncthreads();
    int i = b * 1024 + threadIdx.x;
    if (i < NN) {
        g_rowptr[i] += s_off;
        g_fill[i] = 0;
        g_deg[i]  = 0;
    }
    if (b == 0 && threadIdx.x == 0) g_rowptr[NN] = NET;
}

__global__ void k_fill(const int* __restrict__ ei) {
    int e = blockIdx.x * blockDim.x + threadIdx.x;
    if (e >= NET) return;
    int s, d;
    if (e < NE) { s = ei[e]; d = ei[NE + e]; }
    else        { s = d = e - NE; }                    // self loop
    int p = g_rowptr[d] + atomicAdd(&g_fill[d], 1);
    g_edge[p] = make_int2(s, __float_as_int(g_dinv[s] * g_dinv[d]));
}

// ================= shared HMMA plumbing (sm_80+ PTX; valid on compute_103) =================
#define LDH 136                        // row stride in halves (16B-aligned, conflict-free)
#define GT_BLOCKS ((NN + 127) / 128)

__device__ __forceinline__ uint32_t smem_u32(const void* p) {
    uint32_t a;
    asm("{ .reg .u64 t; cvta.to.shared.u64 t, %1; cvt.u32.u64 %0, t; }" : "=r"(a) : "l"(p));
    return a;
}
__device__ __forceinline__ void ldmx4(uint32_t& r0, uint32_t& r1, uint32_t& r2, uint32_t& r3,
                                      uint32_t addr) {
    asm volatile("ldmatrix.sync.aligned.m8n8.x4.shared.b16 {%0,%1,%2,%3}, [%4];"
                 : "=r"(r0), "=r"(r1), "=r"(r2), "=r"(r3) : "r"(addr));
}
__device__ __forceinline__ void ldmx2(uint32_t& r0, uint32_t& r1, uint32_t addr) {
    asm volatile("ldmatrix.sync.aligned.m8n8.x2.shared.b16 {%0,%1}, [%2];"
                 : "=r"(r0), "=r"(r1) : "r"(addr));
}
__device__ __forceinline__ void mma16816(float* c, uint32_t a0, uint32_t a1, uint32_t a2,
                                         uint32_t a3, uint32_t b0, uint32_t b1) {
    asm volatile(
        "mma.sync.aligned.m16n8k16.row.col.f32.f16.f16.f32 "
        "{%0,%1,%2,%3}, {%4,%5,%6,%7}, {%8,%9}, {%0,%1,%2,%3};"
        : "+f"(c[0]), "+f"(c[1]), "+f"(c[2]), "+f"(c[3])
        : "r"(a0), "r"(a1), "r"(a2), "r"(a3), "r"(b0), "r"(b1));
}

// ================= HMMA GEMM: g_hh = fp16(A @ W) ; A from fp32 (layer 0) or fp16 g_ah (layer 1) =================
#define SM_Ah 0
#define SM_Bh (128 * LDH)
#define SMEM_TC (2 * 128 * LDH * 2)    // 69,632 B

__global__ __launch_bounds__(256) void k_gemm_tc(const float* __restrict__ Aext,
                                                 const float* __restrict__ W, int layer) {
    extern __shared__ __half smem[];
    int tid  = threadIdx.x;
    int wid  = tid >> 5;
    int lane = tid & 31;
    int row0 = blockIdx.x * 128;

    if (layer == 0) {
        // A tile fp32 -> fp16
        #pragma unroll
        for (int it = 0; it < 8; it++) {
            int i   = tid + it * 256;
            int row = i >> 4;
            int cc  = (i & 15) * 8;
            float4 v0 = make_float4(0.f, 0.f, 0.f, 0.f), v1 = v0;
            int r = row0 + row;
            if (r < NN) {
                v0 = *(const float4*)&Aext[r * FDIM + cc];
                v1 = *(const float4*)&Aext[r * FDIM + cc + 4];
            }
            uint4 pk;
            pk.x = h2_as_u32(__floats2half2_rn(v0.x, v0.y));
            pk.y = h2_as_u32(__floats2half2_rn(v0.z, v0.w));
            pk.z = h2_as_u32(__floats2half2_rn(v1.x, v1.y));
            pk.w = h2_as_u32(__floats2half2_rn(v1.z, v1.w));
            *(uint4*)&smem[SM_Ah + row * LDH + cc] = pk;
        }
    } else {
        // A tile straight fp16 copy from g_ah (16 uint4 per row)
        const uint4* src = (const uint4*)g_ah;
        #pragma unroll
        for (int it = 0; it < 8; it++) {
            int i   = tid + it * 256;        // 2048 uint4 chunks
            int row = i >> 4;
            int cc  = (i & 15) * 8;          // column in halves
            uint4 pk = make_uint4(0u, 0u, 0u, 0u);
            int r = row0 + row;
            if (r < NN) pk = src[r * 16 + (i & 15)];
            *(uint4*)&smem[SM_Ah + row * LDH + cc] = pk;
        }
    }
    // BT[n][k] = W[k][n]
    {
        int n  = tid & 127;
        int k0 = (tid >> 7) * 64;
        #pragma unroll 8
        for (int kk = 0; kk < 64; kk++) {
            int k = k0 + kk;
            smem[SM_Bh + n * LDH + k] = __float2half_rn(W[k * FDIM + n]);
        }
    }
    __syncthreads();

    uint32_t sbA = smem_u32(&smem[SM_Ah]);
    uint32_t sbB = smem_u32(&smem[SM_Bh]);
    int m0 = (wid >> 1) * 32;
    int n0 = (wid & 1) * 64;

    float c[2][8][4];
    #pragma unroll
    for (int mi = 0; mi < 2; mi++)
        #pragma unroll
        for (int nj = 0; nj < 8; nj++)
            #pragma unroll
            for (int q = 0; q < 4; q++) c[mi][nj][q] = 0.f;

    int a_row = lane & 15;
    int a_kof = (lane >> 4) * 8;
    int b_row = lane & 7;
    int b_kof = ((lane >> 3) & 1) * 8;

    #pragma unroll
    for (int ks = 0; ks < 8; ks++) {
        int k0 = ks * 16;
        uint32_t a[2][4];
        #pragma unroll
        for (int mi = 0; mi < 2; mi++) {
            uint32_t addr = sbA + (uint32_t)((m0 + mi * 16 + a_row) * LDH + k0 + a_kof) * 2;
            ldmx4(a[mi][0], a[mi][1], a[mi][2], a[mi][3], addr);
        }
        uint32_t b[8][2];
        #pragma unroll
        for (int nj = 0; nj < 8; nj++) {
            uint32_t addr = sbB + (uint32_t)((n0 + nj * 8 + b_row) * LDH + k0 + b_kof) * 2;
            ldmx2(b[nj][0], b[nj][1], addr);
        }
        #pragma unroll
        for (int mi = 0; mi < 2; mi++)
            #pragma unroll
            for (int nj = 0; nj < 8; nj++)
                mma16816(c[mi][nj], a[mi][0], a[mi][1], a[mi][2], a[mi][3],
                         b[nj][0], b[nj][1]);
    }

    int tr = lane >> 2;
    int tc = (lane & 3) * 2;
    #pragma unroll
    for (int mi = 0; mi < 2; mi++) {
        #pragma unroll
        for (int nj = 0; nj < 8; nj++) {
            int col = n0 + nj * 8 + tc;
            int r0g = row0 + m0 + mi * 16 + tr;
            int r1g = r0g + 8;
            if (r0g < NN)
                g_hh[r0g * (FDIM/2) + (col >> 1)] = __floats2half2_rn(c[mi][nj][0], c[mi][nj][1]);
            if (r1g < NN)
                g_hh[r1g * (FDIM/2) + (col >> 1)] = __floats2half2_rn(c[mi][nj][2], c[mi][nj][3]);
        }
    }
}

// ---------------- CSR pull-aggregation (warp-per-node, 50000 warps) ----------------
// mode 0: out = fp16 g_ah, relu(acc + bias)      (layer 1)
// mode 1: out = fp32 outext, acc + bias          (layer 2 -> xemb)
__global__ __launch_bounds__(256) void k_agg(const float* __restrict__ bias,
                                             float* __restrict__ outext, int mode) {
    int gw   = (blockIdx.x * blockDim.x + threadIdx.x) >> 5;   // warp = node
    int lane = threadIdx.x & 31;
    if (gw >= NN) return;
    int p0 = g_rowptr[gw], p1 = g_rowptr[gw + 1];
    float4 acc = make_float4(0.f, 0.f, 0.f, 0.f);
    const uint2* hh = (const uint2*)g_hh;          // 8B = 4 halves; row = 32 uint2
    for (int p = p0; p < p1; p++) {
        int2  e = g_edge[p];
        float w = __int_as_float(e.y);
        uint2 v = hh[e.x * 32 + lane];
        float2 f0 = __half22float2(u32_as_h2(v.x));
        float2 f1 = __half22float2(u32_as_h2(v.y));
        acc.x += w * f0.x; acc.y += w * f0.y;
        acc.z += w * f1.x; acc.w += w * f1.y;
    }
    float4 b = *(const float4*)&bias[lane * 4];
    acc.x += b.x; acc.y += b.y; acc.z += b.z; acc.w += b.w;
    if (mode == 0) {
        acc.x = fmaxf(acc.x, 0.f); acc.y = fmaxf(acc.y, 0.f);
        acc.z = fmaxf(acc.z, 0.f); acc.w = fmaxf(acc.w, 0.f);
        uint2 st;
        st.x = h2_as_u32(__floats2half2_rn(acc.x, acc.y));
        st.y = h2_as_u32(__floats2half2_rn(acc.z, acc.w));
        ((uint2*)g_ah)[gw * 32 + lane] = st;
    } else {
        *(float4*)&outext[gw * FDIM + lane * 4] = acc;
    }
}

// ============ HMMA head: log_softmax(X @ Wl + bl) with split-fp16 (fp32-accurate) ============
#define LG_XhO 0
#define LG_XlO (128 * LDH)
#define LG_WhO (2 * 128 * LDH)
#define LG_WlO (2 * 128 * LDH + CDIM * LDH)
#define LG_BLO (2 * 128 * LDH + 2 * CDIM * LDH)      // half-index where bias floats start
#define SMEM_LG (LG_BLO * 2 + CDIM * 4)

__global__ __launch_bounds__(256) void k_logits_tc(const float* __restrict__ X,
                                                   const float* __restrict__ Wl,
                                                   const float* __restrict__ bl,
                                                   float* __restrict__ out) {
    extern __shared__ __half smem[];
    float* sbl = (float*)&smem[LG_BLO];
    int tid  = threadIdx.x;
    int wid  = tid >> 5;
    int lane = tid & 31;
    int row0 = blockIdx.x * 128;

    #pragma unroll
    for (int it = 0; it < 8; it++) {
        int i   = tid + it * 256;
        int row = i >> 4;
        int cc  = (i & 15) * 8;
        float v[8] = {0.f, 0.f, 0.f, 0.f, 0.f, 0.f, 0.f, 0.f};
        int r = row0 + row;
        if (r < NN) {
            *(float4*)&v[0] = *(const float4*)&X[r * FDIM + cc];
            *(float4*)&v[4] = *(const float4*)&X[r * FDIM + cc + 4];
        }
        __half hi[8], lo[8];
        #pragma unroll
        for (int q = 0; q < 8; q++) {
            hi[q] = __float2half_rn(v[q]);
            lo[q] = __float2half_rn(v[q] - __half2float(hi[q]));
        }
        *(uint4*)&smem[LG_XhO + row * LDH + cc] = *(uint4*)hi;
        *(uint4*)&smem[LG_XlO + row * LDH + cc] = *(uint4*)lo;
    }
    for (int idx = tid; idx < CDIM * FDIM; idx += 256) {
        int n = idx >> 7;
        int k = idx & 127;
        float f = Wl[k * CDIM + n];
        __half h = __float2half_rn(f);
        smem[LG_WhO + n * LDH + k] = h;
        smem[LG_WlO + n * LDH + k] = __float2half_rn(f - __half2float(h));
    }
    if (tid < CDIM) sbl[tid] = bl[tid];
    __syncthreads();

    uint32_t sbXh = smem_u32(&smem[LG_XhO]);
    uint32_t sbXl = smem_u32(&smem[LG_XlO]);
    uint32_t sbWh = smem_u32(&smem[LG_WhO]);
    uint32_t sbWl = smem_u32(&smem[LG_WlO]);

    int m0 = wid * 16;
    float c[5][4];
    #pragma unroll
    for (int nj = 0; nj < 5; nj++)
        #pragma unroll
        for (int q = 0; q < 4; q++) c[nj][q] = 0.f;

    int a_row = lane & 15;
    int a_kof = (lane >> 4) * 8;
    int b_row = lane & 7;
    int b_kof = ((lane >> 3) & 1) * 8;

    #pragma unroll
    for (int ks = 0; ks < 8; ks++) {
        int k0 = ks * 16;
        uint32_t ah[4], al[4];
        uint32_t aaddr = (uint32_t)((m0 + a_row) * LDH + k0 + a_kof) * 2;
        ldmx4(ah[0], ah[1], ah[2], ah[3], sbXh + aaddr);
        ldmx4(al[0], al[1], al[2], al[3], sbXl + aaddr);
        #pragma unroll
        for (int nj = 0; nj < 5; nj++) {
            uint32_t baddr = (uint32_t)((nj * 8 + b_row) * LDH + k0 + b_kof) * 2;
            uint32_t bh0, bh1, bl0, bl1;
            ldmx2(bh0, bh1, sbWh + baddr);
            ldmx2(bl0, bl1, sbWl + baddr);
            mma16816(c[nj], ah[0], ah[1], ah[2], ah[3], bh0, bh1);   // xh*wh
            mma16816(c[nj], al[0], al[1], al[2], al[3], bh0, bh1);   // xl*wh
            mma16816(c[nj], ah[0], ah[1], ah[2], ah[3], bl0, bl1);   // xh*wl
        }
    }

    int tr  = lane >> 2;
    int tc2 = (lane & 3) * 2;
    #pragma unroll
    for (int nj = 0; nj < 5; nj++) {
        float b0 = sbl[nj * 8 + tc2], b1v = sbl[nj * 8 + tc2 + 1];
        c[nj][0] += b0; c[nj][1] += b1v;
        c[nj][2] += b0; c[nj][3] += b1v;
    }

    float mA = -INFINITY, mB = -INFINITY;
    #pragma unroll
    for (int nj = 0; nj < 5; nj++) {
        mA = fmaxf(mA, fmaxf(c[nj][0], c[nj][1]));
        mB = fmaxf(mB, fmaxf(c[nj][2], c[nj][3]));
    }
    mA = fmaxf(mA, __shfl_xor_sync(0xffffffffu, mA, 1));
    mA = fmaxf(mA, __shfl_xor_sync(0xffffffffu, mA, 2));
    mB = fmaxf(mB, __shfl_xor_sync(0xffffffffu, mB, 1));
    mB = fmaxf(mB, __shfl_xor_sync(0xffffffffu, mB, 2));
    float sA = 0.f, sB = 0.f;
    #pragma unroll
    for (int nj = 0; nj < 5; nj++) {
        sA += expf(c[nj][0] - mA) + expf(c[nj][1] - mA);
        sB += expf(c[nj][2] - mB) + expf(c[nj][3] - mB);
    }
    sA += __shfl_xor_sync(0xffffffffu, sA, 1);
    sA += __shfl_xor_sync(0xffffffffu, sA, 2);
    sB += __shfl_xor_sync(0xffffffffu, sB, 1);
    sB += __shfl_xor_sync(0xffffffffu, sB, 2);
    float dA = mA + logf(sA), dB = mB + logf(sB);

    int rA = row0 + m0 + tr;
    int rB = rA + 8;
    #pragma unroll
    for (int nj = 0; nj < 5; nj++) {
        int col = nj * 8 + tc2;
        if (rA < NN) {
            float2 o = make_float2(c[nj][0] - dA, c[nj][1] - dA);
            *(float2*)&out[rA * CDIM + col] = o;
        }
        if (rB < NN) {
            float2 o = make_float2(c[nj][2] - dB, c[nj][3] - dB);
            *(float2*)&out[rB * CDIM + col] = o;
        }
    }
}

// ---------------- launcher (graph-capture safe; fork gemm1 beside preproc) ----------------
extern "C" void kernel_launch(void* const* d_in, const int* in_sizes, int n_in,
                              void* d_out, int out_size) {
    const float* x  = (const float*)d_in[0];
    const int*   ei = (const int*)d_in[1];     // JAX int64 request silently yields int32
    const float* W1 = (const float*)d_in[2];
    const float* b1 = (const float*)d_in[3];
    const float* W2 = (const float*)d_in[4];
    const float* b2 = (const float*)d_in[5];
    const float* Wl = (const float*)d_in[6];
    const float* bl = (const float*)d_in[7];
    float* out  = (float*)d_out;
    float* xemb = out + (size_t)NN * CDIM;     // second output lives after logits

    cudaFuncSetAttribute(k_gemm_tc,   cudaFuncAttributeMaxDynamicSharedMemorySize, SMEM_TC);
    cudaFuncSetAttribute(k_logits_tc, cudaFuncAttributeMaxDynamicSharedMemorySize, SMEM_LG);

    // fork: gemm1 depends only on (x, W1) — run beside the preproc chain.
    cudaStream_t s2;
    cudaEvent_t  evFork, evJoin;
    cudaStreamCreateWithFlags(&s2, cudaStreamNonBlocking);
    cudaEventCreateWithFlags(&evFork, cudaEventDisableTiming);
    cudaEventCreateWithFlags(&evJoin, cudaEventDisableTiming);

    cudaEventRecord(evFork, 0);
    cudaStreamWaitEvent(s2, evFork, 0);
    k_gemm_tc<<<GT_BLOCKS, 256, SMEM_TC, s2>>>(x, W1, 0);   // layer-1 GEMM on side branch
    cudaEventRecord(evJoin, s2);

    // preprocessing chain on the main (capture) stream
    k_hist <<<(NE + 255) / 256, 256>>>(ei);
    k_scan1<<<NSCB, 1024>>>();
    k_scan3<<<NSCB, 1024>>>();
    k_fill <<<(NET + 255) / 256, 256>>>(ei);

    cudaStreamWaitEvent(0, evJoin, 0);   // join: agg1 needs both CSR and g_hh

    int agg_blocks = (NN * 32 + 255) / 256;

    // layer 1 aggregation: g_ah = fp16(relu(agg(g_hh) + b1))
    k_agg<<<agg_blocks, 256>>>(b1, nullptr, 0);

    // layer 2: g_hh = fp16(g_ah @ W2) ; xemb = agg(g_hh) + b2
    k_gemm_tc<<<GT_BLOCKS, 256, SMEM_TC>>>(nullptr, W2, 1);
    k_agg<<<agg_blocks, 256>>>(b2, xemb, 1);

    // head: log_softmax(xemb @ Wl + bl) via split-fp16 HMMA
    k_logits_tc<<<GT_BLOCKS, 256, SMEM_LG>>>(xemb, Wl, bl, out);
}